// round 5
// baseline (speedup 1.0000x reference)
#include <cuda_runtime.h>

// ---------------- problem constants ----------------
constexpr int NUc = 100000;
constexpr int NIc = 50000;
constexpr int Dc  = 64;
constexpr int EBc = 500000;
constexpr int ECc = 1000000;
constexpr int EPc = 2000000;
constexpr int ETOT_E = EBc + ECc + EPc;   // 3.5M

constexpr int NUD = NUc * Dc;  // 6.4M
constexpr int NID = NIc * Dc;  // 3.2M

constexpr float A_SC = 0.0045f;
constexpr float B_SC = 0.0045f;

// zbuf layout: aggU[3][NUD] | aggD[3][NID] | se[3][NUD] | de[3][NID]
constexpr size_t ZB_AGGU = 0;
constexpr size_t ZB_AGGD = (size_t)3 * NUD;
constexpr size_t ZB_SE   = ZB_AGGD + (size_t)3 * NID;
constexpr size_t ZB_DE   = ZB_SE + (size_t)3 * NUD;
constexpr size_t ZTOT    = ZB_DE + (size_t)3 * NID;

// unified scan domain: [3*NU user slots | 3*NI item slots]
constexpr int SCAN_ALL  = 3 * (NUc + NIc);              // 450K
constexpr int NBLK_SCAN = (SCAN_ALL + 1023) / 1024;     // 440
constexpr int CSR_TOT   = 2 * ETOT_E;                   // 7M (each edge in u- and v-list)

// ---------------- device scratch (no allocation allowed) ----------------
__device__ float g_zbuf[ZTOT];
__device__ float g_seW[(size_t)3 * NUD];
__device__ float g_deW[(size_t)3 * NID];
__device__ float g_src[NUD];
__device__ float g_dst[NID];
__device__ float g_srcAll[NUD];
__device__ float g_dstAll[NID];
__device__ int   g_deg[SCAN_ALL];
__device__ float g_isqU[3 * NUc];
__device__ float g_isqV[3 * NIc];
__device__ float g_dU[3 * NUc];
__device__ float g_dV[3 * NIc];
// dual CSR
__device__ int g_csr[CSR_TOT];
__device__ int g_tmpScan[SCAN_ALL];
__device__ int g_blkSum[512];
__device__ int g_blkSumScan[512];
__device__ int g_start[SCAN_ALL];
__device__ int g_cur[SCAN_ALL];

__device__ __forceinline__ float lrelu(float x) { return x >= 0.0f ? x : 0.01f * x; }

// ---------------- setup kernels ----------------

__global__ void zeroDeg_k() {
    int i = blockIdx.x * blockDim.x + threadIdx.x;
    if (i < SCAN_ALL) g_deg[i] = 0;
}

__global__ void degCount_k(int t, const int* __restrict__ U, const int* __restrict__ V, int E) {
    int e = blockIdx.x * blockDim.x + threadIdx.x;
    if (e >= E) return;
    atomicAdd(&g_deg[t * NUc + U[e]], 1);
    atomicAdd(&g_deg[3 * NUc + t * NIc + V[e]], 1);
}

__global__ void degConv_k() {
    int i = blockIdx.x * blockDim.x + threadIdx.x;
    if (i < 3 * NUc) {
        float f = (float)max(g_deg[i], 1);
        g_dU[i] = f;
        g_isqU[i] = rsqrtf(f);
    } else if (i < SCAN_ALL) {
        int j = i - 3 * NUc;
        float f = (float)max(g_deg[i], 1);
        g_dV[j] = f;
        g_isqV[j] = rsqrtf(f);
    }
}

// ---- hierarchical exclusive scan over all 450K degree slots ----
__global__ void blockScan_k() {
    __shared__ int wsum[32];
    int tid = threadIdx.x;
    int gi = blockIdx.x * 1024 + tid;
    int d = (gi < SCAN_ALL) ? g_deg[gi] : 0;
    int x = d;
#pragma unroll
    for (int o = 1; o < 32; o <<= 1) {
        int y = __shfl_up_sync(0xFFFFFFFFu, x, o);
        if ((tid & 31) >= o) x += y;
    }
    if ((tid & 31) == 31) wsum[tid >> 5] = x;
    __syncthreads();
    if (tid < 32) {
        int w = wsum[tid];
#pragma unroll
        for (int o = 1; o < 32; o <<= 1) {
            int y = __shfl_up_sync(0xFFFFFFFFu, w, o);
            if (tid >= o) w += y;
        }
        wsum[tid] = w;
    }
    __syncthreads();
    int incl = x + ((tid >= 32) ? wsum[(tid >> 5) - 1] : 0);
    if (gi < SCAN_ALL) g_tmpScan[gi] = incl - d;
    if (tid == 1023) g_blkSum[blockIdx.x] = incl;
}

__global__ void scanSums_k() {
    __shared__ int wsum[32];
    int tid = threadIdx.x;   // 512 threads, NBLK_SCAN <= 512
    int d = (tid < NBLK_SCAN) ? g_blkSum[tid] : 0;
    int x = d;
#pragma unroll
    for (int o = 1; o < 32; o <<= 1) {
        int y = __shfl_up_sync(0xFFFFFFFFu, x, o);
        if ((tid & 31) >= o) x += y;
    }
    if ((tid & 31) == 31) wsum[tid >> 5] = x;
    __syncthreads();
    if (tid < 32) {
        int w = (tid < 16) ? wsum[tid] : 0;
#pragma unroll
        for (int o = 1; o < 32; o <<= 1) {
            int y = __shfl_up_sync(0xFFFFFFFFu, w, o);
            if (tid >= o) w += y;
        }
        wsum[tid] = w;
    }
    __syncthreads();
    int incl = x + ((tid >= 32) ? wsum[(tid >> 5) - 1] : 0);
    if (tid < NBLK_SCAN) g_blkSumScan[tid] = incl;
}

__global__ void addOff_k() {
    int gi = blockIdx.x * 1024 + threadIdx.x;
    if (gi >= SCAN_ALL) return;
    int blk = gi >> 10;
    int s = g_tmpScan[gi] + (blk ? g_blkSumScan[blk - 1] : 0);
    g_start[gi] = s;
    g_cur[gi] = s;
}

__global__ void csrFill_k(int t, const int* __restrict__ U, const int* __restrict__ V, int E) {
    int e = blockIdx.x * blockDim.x + threadIdx.x;
    if (e >= E) return;
    int pu = atomicAdd(&g_cur[t * NUc + U[e]], 1);
    g_csr[pu] = e;
    int pv = atomicAdd(&g_cur[3 * NUc + t * NIc + V[e]], 1);
    g_csr[pv] = e;
}

__global__ void scaleInit_k(const float* __restrict__ emb, int items) {
    int i = blockIdx.x * blockDim.x + threadIdx.x;
    int n = items ? NID : NUD;
    if (i >= n) return;
    float v = emb[i] * A_SC;
    if (items) { g_dst[i] = v; g_dstAll[i] = v; }
    else       { g_src[i] = v; g_srcAll[i] = v; }
}

// ---------------- layer-0 pure-gather passes (no atomics) ----------------
// u-side: accumulate aggU = sum_v dst[v]*isqV[v]*w  and  se = sum w
__global__ void __launch_bounds__(256) gathU0_k(const float* __restrict__ ew,
                                                int t, const int* __restrict__ V) {
    int gid = blockIdx.x * 256 + threadIdx.x;
    int u = gid >> 4, q = gid & 15;
    if (u >= NUc) return;
    int si = t * NUc + u;
    int beg = g_start[si];
    int end = (si + 1 < SCAN_ALL) ? g_start[si + 1] : CSR_TOT;

    float4 accU = make_float4(0.f, 0.f, 0.f, 0.f);
    float4 accSe = make_float4(0.f, 0.f, 0.f, 0.f);

    int i = beg;
    int e_n = 0, v_n = 0;
    if (i < end) { e_n = __ldg(g_csr + i); v_n = __ldg(V + e_n); }
    while (i < end) {
        int e = e_n, v = v_n;
        i++;
        if (i < end) { e_n = __ldg(g_csr + i); v_n = __ldg(V + e_n); }
        float sv = g_isqV[t * NIc + v];
        float4 w = __ldcs((const float4*)ew + (size_t)e * 16 + q);
        float4 d = __ldg((const float4*)g_dst + v * 16 + q);
        accU.x = fmaf(d.x * sv, w.x, accU.x);
        accU.y = fmaf(d.y * sv, w.y, accU.y);
        accU.z = fmaf(d.z * sv, w.z, accU.z);
        accU.w = fmaf(d.w * sv, w.w, accU.w);
        accSe.x += w.x; accSe.y += w.y; accSe.z += w.z; accSe.w += w.w;
    }
    // B_SC folded in at the end (linear)
    accU.x *= B_SC; accU.y *= B_SC; accU.z *= B_SC; accU.w *= B_SC;
    accSe.x *= B_SC; accSe.y *= B_SC; accSe.z *= B_SC; accSe.w *= B_SC;
    ((float4*)(g_zbuf + ZB_AGGU + (size_t)t * NUD))[u * 16 + q] = accU;
    ((float4*)(g_zbuf + ZB_SE   + (size_t)t * NUD))[u * 16 + q] = accSe;
}

// v-side: accumulate aggD = sum_u src[u]*isqU[u]*w  and  de = sum w
__global__ void __launch_bounds__(256) gathV0_k(const float* __restrict__ ew,
                                                int t, const int* __restrict__ U) {
    int gid = blockIdx.x * 256 + threadIdx.x;
    int v = gid >> 4, q = gid & 15;
    if (v >= NIc) return;
    int si = 3 * NUc + t * NIc + v;
    int beg = g_start[si];
    int end = (si + 1 < SCAN_ALL) ? g_start[si + 1] : CSR_TOT;

    float4 accD = make_float4(0.f, 0.f, 0.f, 0.f);
    float4 accDe = make_float4(0.f, 0.f, 0.f, 0.f);

    int i = beg;
    int e_n = 0, u_n = 0;
    if (i < end) { e_n = __ldg(g_csr + i); u_n = __ldg(U + e_n); }
    while (i < end) {
        int e = e_n, u = u_n;
        i++;
        if (i < end) { e_n = __ldg(g_csr + i); u_n = __ldg(U + e_n); }
        float su = g_isqU[t * NUc + u];
        float4 w = __ldcs((const float4*)ew + (size_t)e * 16 + q);
        float4 s = __ldg((const float4*)g_src + u * 16 + q);
        accD.x = fmaf(s.x * su, w.x, accD.x);
        accD.y = fmaf(s.y * su, w.y, accD.y);
        accD.z = fmaf(s.z * su, w.z, accD.z);
        accD.w = fmaf(s.w * su, w.w, accD.w);
        accDe.x += w.x; accDe.y += w.y; accDe.z += w.z; accDe.w += w.w;
    }
    accD.x *= B_SC; accD.y *= B_SC; accD.z *= B_SC; accD.w *= B_SC;
    accDe.x *= B_SC; accDe.y *= B_SC; accDe.z *= B_SC; accDe.w *= B_SC;
    ((float4*)(g_zbuf + ZB_AGGD + (size_t)t * NID))[v * 16 + q] = accD;
    ((float4*)(g_zbuf + ZB_DE   + (size_t)t * NID))[v * 16 + q] = accDe;
}

// ---------------- layer-1 pure-gather passes (edge weight inline) ----------------
// w = lrelu((seW[u]+deW[v]) / (dU[u]+dV[v]))
__global__ void __launch_bounds__(256) gathU1_k(int t, const int* __restrict__ V) {
    int gid = blockIdx.x * 256 + threadIdx.x;
    int u = gid >> 4, q = gid & 15;
    if (u >= NUc) return;
    int si = t * NUc + u;
    float du = g_dU[si];
    float4 sw = ((const float4*)g_seW)[(size_t)t * NUc * 16 + u * 16 + q];
    int beg = g_start[si];
    int end = (si + 1 < SCAN_ALL) ? g_start[si + 1] : CSR_TOT;

    float4 accU = make_float4(0.f, 0.f, 0.f, 0.f);

    int i = beg;
    int e_n = 0, v_n = 0;
    if (i < end) { e_n = __ldg(g_csr + i); v_n = __ldg(V + e_n); }
    while (i < end) {
        int v = v_n;
        i++;
        if (i < end) { e_n = __ldg(g_csr + i); v_n = __ldg(V + e_n); }
        float sv = g_isqV[t * NIc + v];
        float r = 1.0f / (du + g_dV[t * NIc + v]);
        float4 dw = __ldg((const float4*)g_deW + (size_t)t * NIc * 16 + v * 16 + q);
        float4 w;
        w.x = lrelu((sw.x + dw.x) * r);
        w.y = lrelu((sw.y + dw.y) * r);
        w.z = lrelu((sw.z + dw.z) * r);
        w.w = lrelu((sw.w + dw.w) * r);
        float4 d = __ldg((const float4*)g_dst + v * 16 + q);
        accU.x = fmaf(d.x * sv, w.x, accU.x);
        accU.y = fmaf(d.y * sv, w.y, accU.y);
        accU.z = fmaf(d.z * sv, w.z, accU.z);
        accU.w = fmaf(d.w * sv, w.w, accU.w);
    }
    ((float4*)(g_zbuf + ZB_AGGU + (size_t)t * NUD))[u * 16 + q] = accU;
}

__global__ void __launch_bounds__(256) gathV1_k(int t, const int* __restrict__ U) {
    int gid = blockIdx.x * 256 + threadIdx.x;
    int v = gid >> 4, q = gid & 15;
    if (v >= NIc) return;
    int si = 3 * NUc + t * NIc + v;
    float dv = g_dV[t * NIc + v];
    float4 dw = ((const float4*)g_deW)[(size_t)t * NIc * 16 + v * 16 + q];
    int beg = g_start[si];
    int end = (si + 1 < SCAN_ALL) ? g_start[si + 1] : CSR_TOT;

    float4 accD = make_float4(0.f, 0.f, 0.f, 0.f);

    int i = beg;
    int e_n = 0, u_n = 0;
    if (i < end) { e_n = __ldg(g_csr + i); u_n = __ldg(U + e_n); }
    while (i < end) {
        int u = u_n;
        i++;
        if (i < end) { e_n = __ldg(g_csr + i); u_n = __ldg(U + e_n); }
        float su = g_isqU[t * NUc + u];
        float r = 1.0f / (g_dU[t * NUc + u] + dv);
        float4 sw = __ldg((const float4*)g_seW + (size_t)t * NUc * 16 + u * 16 + q);
        float4 w;
        w.x = lrelu((sw.x + dw.x) * r);
        w.y = lrelu((sw.y + dw.y) * r);
        w.z = lrelu((sw.z + dw.z) * r);
        w.w = lrelu((sw.w + dw.w) * r);
        float4 s = __ldg((const float4*)g_src + u * 16 + q);
        accD.x = fmaf(s.x * su, w.x, accD.x);
        accD.y = fmaf(s.y * su, w.y, accD.y);
        accD.z = fmaf(s.z * su, w.z, accD.z);
        accD.w = fmaf(s.w * su, w.w, accD.w);
    }
    ((float4*)(g_zbuf + ZB_AGGD + (size_t)t * NID))[v * 16 + q] = accD;
}

// ---------------- node kernels ----------------

__global__ void nodeCombine_k(const float* __restrict__ W, int items) {
    __shared__ float Ws[64 * 64];
    __shared__ float R[4][3][64];
    int tx = threadIdx.x, ty = threadIdx.y;
    int lin = ty * 64 + tx;
#pragma unroll
    for (int i = 0; i < 16; i++) Ws[lin + 256 * i] = W[lin + 256 * i];

    int N = items ? NIc : NUc;
    int nd = items ? NID : NUD;
    int n = blockIdx.x * 4 + ty;
    const float* agg = items ? (g_zbuf + ZB_AGGD) : (g_zbuf + ZB_AGGU);
    if (n < N) {
        R[ty][0][tx] = agg[(size_t)0 * nd + n * 64 + tx];
        R[ty][1][tx] = agg[(size_t)1 * nd + n * 64 + tx];
        R[ty][2][tx] = agg[(size_t)2 * nd + n * 64 + tx];
    }
    __syncthreads();
    if (n >= N) return;

    float s0 = 0.f, s1 = 0.f, s2 = 0.f;
#pragma unroll
    for (int k = 0; k < 64; k++) {
        float wk = Ws[k * 64 + tx];
        s0 = fmaf(R[ty][0][k], wk, s0);
        s1 = fmaf(R[ty][1][k], wk, s1);
        s2 = fmaf(R[ty][2][k], wk, s2);
    }
    const float* isq = items ? g_isqV : g_isqU;
    int NN = items ? NIc : NUc;
    float o = lrelu(s0 * isq[0 * NN + n]) + 0.5f * lrelu(s1 * isq[1 * NN + n])
            + 0.25f * lrelu(s2 * isq[2 * NN + n]);
    float* cur = items ? g_dst : g_src;
    float* acc = items ? g_dstAll : g_srcAll;
    cur[n * 64 + tx] = o;
    acc[n * 64 + tx] += o;
}

__global__ void seGemm_k(const float* __restrict__ W, int t, int items) {
    __shared__ float Ws[64 * 64];
    __shared__ float R[4][64];
    int tx = threadIdx.x, ty = threadIdx.y;
    int lin = ty * 64 + tx;
#pragma unroll
    for (int i = 0; i < 16; i++) Ws[lin + 256 * i] = W[lin + 256 * i];

    int N = items ? NIc : NUc;
    const float* in  = items ? (g_zbuf + ZB_DE + (size_t)t * NID)
                             : (g_zbuf + ZB_SE + (size_t)t * NUD);
    float* out = items ? (g_deW + (size_t)t * NID) : (g_seW + (size_t)t * NUD);
    int n = blockIdx.x * 4 + ty;
    if (n < N) R[ty][tx] = in[n * 64 + tx];
    __syncthreads();
    if (n >= N) return;

    float s = 0.f;
#pragma unroll
    for (int k = 0; k < 64; k++) s = fmaf(R[ty][k], Ws[k * 64 + tx], s);
    out[n * 64 + tx] = s;
}

__global__ void writeOut_k(float* __restrict__ out) {
    int i = blockIdx.x * blockDim.x + threadIdx.x;
    if (i < NUD) out[i] = g_srcAll[i] / 3.0f;
    else if (i < NUD + NID) out[i] = g_dstAll[i - NUD] / 3.0f;
}

// ---------------- launch ----------------
extern "C" void kernel_launch(void* const* d_in, const int* in_sizes, int n_in,
                              void* d_out, int out_size) {
    const float* user  = (const float*)d_in[0];
    const float* item  = (const float*)d_in[1];
    const float* ebuy  = (const float*)d_in[2];
    const float* ecart = (const float*)d_in[3];
    const float* epv   = (const float*)d_in[4];
    const float* nodeW = (const float*)d_in[5];
    const float* edgeW = (const float*)d_in[6];
    const int* bu = (const int*)d_in[7];
    const int* bv = (const int*)d_in[8];
    const int* cu = (const int*)d_in[9];
    const int* cv = (const int*)d_in[10];
    const int* pu = (const int*)d_in[11];
    const int* pvv = (const int*)d_in[12];
    float* out = (float*)d_out;

    const int TB = 256;
    auto nb = [](long long n, int tb) { return (unsigned)((n + tb - 1) / tb); };

    // degrees
    zeroDeg_k<<<nb(SCAN_ALL, TB), TB>>>();
    degCount_k<<<nb(EBc, TB), TB>>>(0, bu, bv, EBc);
    degCount_k<<<nb(ECc, TB), TB>>>(1, cu, cv, ECc);
    degCount_k<<<nb(EPc, TB), TB>>>(2, pu, pvv, EPc);
    degConv_k<<<nb(SCAN_ALL, TB), TB>>>();

    // dual CSR (u-lists and v-lists via one unified scan)
    blockScan_k<<<NBLK_SCAN, 1024>>>();
    scanSums_k<<<1, 512>>>();
    addOff_k<<<NBLK_SCAN, 1024>>>();
    csrFill_k<<<nb(EBc, TB), TB>>>(0, bu, bv, EBc);
    csrFill_k<<<nb(ECc, TB), TB>>>(1, cu, cv, ECc);
    csrFill_k<<<nb(EPc, TB), TB>>>(2, pu, pvv, EPc);

    scaleInit_k<<<nb(NUD, TB), TB>>>(user, 0);
    scaleInit_k<<<nb(NID, TB), TB>>>(item, 1);

    dim3 bt(64, 4);
    unsigned gU = nb((long long)NUc * 16, 256);
    unsigned gV = nb((long long)NIc * 16, 256);

    // -------- layer 0 (no zeroing needed; every agg word is overwritten) --------
    gathU0_k<<<gU, 256>>>(ebuy, 0, bv);
    gathU0_k<<<gU, 256>>>(ecart, 1, cv);
    gathU0_k<<<gU, 256>>>(epv, 2, pvv);
    gathV0_k<<<gV, 256>>>(ebuy, 0, bu);
    gathV0_k<<<gV, 256>>>(ecart, 1, cu);
    gathV0_k<<<gV, 256>>>(epv, 2, pu);

    nodeCombine_k<<<nb(NIc, 4), bt>>>(nodeW, 1);
    nodeCombine_k<<<nb(NUc, 4), bt>>>(nodeW, 0);

    for (int t = 0; t < 3; t++) {
        seGemm_k<<<nb(NUc, 4), bt>>>(edgeW, t, 0);
        seGemm_k<<<nb(NIc, 4), bt>>>(edgeW, t, 1);
    }

    // -------- layer 1 (edge weights recomputed inline; pure gather) --------
    gathU1_k<<<gU, 256>>>(0, bv);
    gathU1_k<<<gU, 256>>>(1, cv);
    gathU1_k<<<gU, 256>>>(2, pvv);
    gathV1_k<<<gV, 256>>>(0, bu);
    gathV1_k<<<gV, 256>>>(1, cu);
    gathV1_k<<<gV, 256>>>(2, pu);

    nodeCombine_k<<<nb(NIc, 4), bt>>>(nodeW + Dc * Dc, 1);
    nodeCombine_k<<<nb(NUc, 4), bt>>>(nodeW + Dc * Dc, 0);

    writeOut_k<<<nb(NUD + NID, TB), TB>>>(out);
}

// round 6
// speedup vs baseline: 1.1918x; 1.1918x over previous
#include <cuda_runtime.h>

// ---------------- problem constants ----------------
constexpr int NUc = 100000;
constexpr int NIc = 50000;
constexpr int Dc  = 64;
constexpr int EBc = 500000;
constexpr int ECc = 1000000;
constexpr int EPc = 2000000;
constexpr int ETOT_E = EBc + ECc + EPc;   // 3.5M

constexpr int NUD = NUc * Dc;  // 6.4M
constexpr int NID = NIc * Dc;  // 3.2M

constexpr float A_SC = 0.0045f;
constexpr float B_SC = 0.0045f;

// zbuf layout: aggU[3][NUD] | aggD[3][NID] | se[3][NUD] | de[3][NID]
constexpr size_t ZB_AGGU = 0;
constexpr size_t ZB_AGGD = (size_t)3 * NUD;
constexpr size_t ZB_SE   = ZB_AGGD + (size_t)3 * NID;
constexpr size_t ZB_DE   = ZB_SE + (size_t)3 * NUD;
constexpr size_t ZTOT    = ZB_DE + (size_t)3 * NID;

constexpr int SCAN_ALL  = 3 * (NUc + NIc);           // all degree slots (users first)
constexpr int SCAN_N    = 3 * NUc;                   // scan domain (user lists only)
constexpr int NBLK_SCAN = (SCAN_N + 1023) / 1024;    // 293

// ---------------- device scratch (no allocation allowed) ----------------
__device__ float g_zbuf[ZTOT];
__device__ float g_seW[(size_t)3 * NUD];
__device__ float g_deW[(size_t)3 * NID];
__device__ float g_src[NUD];
__device__ float g_dst[NID];
__device__ float g_srcAll[NUD];
__device__ float g_dstAll[NID];
__device__ int   g_deg[SCAN_ALL];
__device__ float g_isqU[3 * NUc];
__device__ float g_isqV[3 * NIc];
__device__ float g_dU[3 * NUc];
__device__ float g_dV[3 * NIc];
// u-side CSR with pre-joined payload: {e, v, bits(isqV[v]), bits(dV[v])}
__device__ int4 g_csrV[ETOT_E];
__device__ int g_tmpScan[SCAN_N];
__device__ int g_blkSum[512];
__device__ int g_blkSumScan[512];
__device__ int g_start[SCAN_N];
__device__ int g_cur[SCAN_N];

__device__ __forceinline__ float lrelu(float x) { return x >= 0.0f ? x : 0.01f * x; }

__device__ __forceinline__ void red4(float4* a, float x, float y, float z, float w) {
    asm volatile("red.global.add.v4.f32 [%0], {%1, %2, %3, %4};"
                 :: "l"(a), "f"(x), "f"(y), "f"(z), "f"(w) : "memory");
}

// ---------------- setup kernels ----------------

__global__ void zeroRange_k(size_t off4, size_t n4) {
    size_t i = (size_t)blockIdx.x * blockDim.x + threadIdx.x;
    if (i < n4) ((float4*)g_zbuf)[off4 + i] = make_float4(0.f, 0.f, 0.f, 0.f);
}

__global__ void zeroDeg_k() {
    int i = blockIdx.x * blockDim.x + threadIdx.x;
    if (i < SCAN_ALL) g_deg[i] = 0;
}

__global__ void degCount_k(int t, const int* __restrict__ U, const int* __restrict__ V, int E) {
    int e = blockIdx.x * blockDim.x + threadIdx.x;
    if (e >= E) return;
    atomicAdd(&g_deg[t * NUc + U[e]], 1);
    atomicAdd(&g_deg[3 * NUc + t * NIc + V[e]], 1);
}

__global__ void degConv_k() {
    int i = blockIdx.x * blockDim.x + threadIdx.x;
    if (i < 3 * NUc) {
        float f = (float)max(g_deg[i], 1);
        g_dU[i] = f;
        g_isqU[i] = rsqrtf(f);
    } else if (i < SCAN_ALL) {
        int j = i - 3 * NUc;
        float f = (float)max(g_deg[i], 1);
        g_dV[j] = f;
        g_isqV[j] = rsqrtf(f);
    }
}

// ---- hierarchical exclusive scan of user-side degrees ----
__global__ void blockScan_k() {
    __shared__ int wsum[32];
    int tid = threadIdx.x;
    int gi = blockIdx.x * 1024 + tid;
    int d = (gi < SCAN_N) ? g_deg[gi] : 0;
    int x = d;
#pragma unroll
    for (int o = 1; o < 32; o <<= 1) {
        int y = __shfl_up_sync(0xFFFFFFFFu, x, o);
        if ((tid & 31) >= o) x += y;
    }
    if ((tid & 31) == 31) wsum[tid >> 5] = x;
    __syncthreads();
    if (tid < 32) {
        int w = wsum[tid];
#pragma unroll
        for (int o = 1; o < 32; o <<= 1) {
            int y = __shfl_up_sync(0xFFFFFFFFu, w, o);
            if (tid >= o) w += y;
        }
        wsum[tid] = w;
    }
    __syncthreads();
    int incl = x + ((tid >= 32) ? wsum[(tid >> 5) - 1] : 0);
    if (gi < SCAN_N) g_tmpScan[gi] = incl - d;
    if (tid == 1023) g_blkSum[blockIdx.x] = incl;
}

__global__ void scanSums_k() {
    __shared__ int wsum[32];
    int tid = threadIdx.x;   // 512 threads, NBLK_SCAN <= 512
    int d = (tid < NBLK_SCAN) ? g_blkSum[tid] : 0;
    int x = d;
#pragma unroll
    for (int o = 1; o < 32; o <<= 1) {
        int y = __shfl_up_sync(0xFFFFFFFFu, x, o);
        if ((tid & 31) >= o) x += y;
    }
    if ((tid & 31) == 31) wsum[tid >> 5] = x;
    __syncthreads();
    if (tid < 32) {
        int w = (tid < 16) ? wsum[tid] : 0;
#pragma unroll
        for (int o = 1; o < 32; o <<= 1) {
            int y = __shfl_up_sync(0xFFFFFFFFu, w, o);
            if (tid >= o) w += y;
        }
        wsum[tid] = w;
    }
    __syncthreads();
    int incl = x + ((tid >= 32) ? wsum[(tid >> 5) - 1] : 0);
    if (tid < NBLK_SCAN) g_blkSumScan[tid] = incl;
}

__global__ void addOff_k() {
    int gi = blockIdx.x * 1024 + threadIdx.x;
    if (gi >= SCAN_N) return;
    int blk = gi >> 10;
    int s = g_tmpScan[gi] + (blk ? g_blkSumScan[blk - 1] : 0);
    g_start[gi] = s;
    g_cur[gi] = s;
}

// pack {e, v, isqV[v], dV[v]} so gather loops have a depth-2 load chain
__global__ void csrFill_k(int t, const int* __restrict__ U, const int* __restrict__ V, int E) {
    int e = blockIdx.x * blockDim.x + threadIdx.x;
    if (e >= E) return;
    int u = U[e], v = V[e];
    int p = atomicAdd(&g_cur[t * NUc + u], 1);
    g_csrV[p] = make_int4(e, v, __float_as_int(g_isqV[t * NIc + v]),
                          __float_as_int(g_dV[t * NIc + v]));
}

__global__ void scaleInit_k(const float* __restrict__ emb, int items) {
    int i = blockIdx.x * blockDim.x + threadIdx.x;
    int n = items ? NID : NUD;
    if (i >= n) return;
    float v = emb[i] * A_SC;
    if (items) { g_dst[i] = v; g_dstAll[i] = v; }
    else       { g_src[i] = v; g_srcAll[i] = v; }
}

// ---------------- layer-0 edge pass (unroll-4, pre-joined CSR) ----------------
// regs accumulate aggU (dst-gather) and se_raw; REDs scatter aggD and de_raw.
// B_SC folded into ssu (for aggD RED) and end-scale (for aggU); se/de stay raw,
// compensated inside seGemm's weight load.
__global__ void __launch_bounds__(256) gath0_k(const float* __restrict__ ew,
                                               int t, int tbase) {
    int gid = blockIdx.x * 256 + threadIdx.x;
    int u = gid >> 4, q = gid & 15;
    if (u >= NUc) return;
    int si = t * NUc + u;
    float su = g_isqU[si] * B_SC;
    float4 s = ((const float4*)g_src)[u * 16 + q];
    float4 ssu = make_float4(s.x * su, s.y * su, s.z * su, s.w * su);
    int beg = g_start[si];
    int end = (si + 1 < SCAN_N) ? g_start[si + 1] : ETOT_E;

    float4 accU = make_float4(0.f, 0.f, 0.f, 0.f);
    float4 accSe = make_float4(0.f, 0.f, 0.f, 0.f);
    float4* aggD = (float4*)(g_zbuf + ZB_AGGD + (size_t)t * NID);
    float4* de   = (float4*)(g_zbuf + ZB_DE   + (size_t)t * NID);

    int i = beg;
#pragma unroll 1
    for (; i + 4 <= end; i += 4) {
        int4 c0 = __ldg(g_csrV + i + 0);
        int4 c1 = __ldg(g_csrV + i + 1);
        int4 c2 = __ldg(g_csrV + i + 2);
        int4 c3 = __ldg(g_csrV + i + 3);
        float4 w0 = __ldcs((const float4*)ew + (size_t)c0.x * 16 + q);
        float4 w1 = __ldcs((const float4*)ew + (size_t)c1.x * 16 + q);
        float4 w2 = __ldcs((const float4*)ew + (size_t)c2.x * 16 + q);
        float4 w3 = __ldcs((const float4*)ew + (size_t)c3.x * 16 + q);
        float4 d0 = __ldg((const float4*)g_dst + c0.y * 16 + q);
        float4 d1 = __ldg((const float4*)g_dst + c1.y * 16 + q);
        float4 d2 = __ldg((const float4*)g_dst + c2.y * 16 + q);
        float4 d3 = __ldg((const float4*)g_dst + c3.y * 16 + q);
        float sv0 = __int_as_float(c0.z), sv1 = __int_as_float(c1.z);
        float sv2 = __int_as_float(c2.z), sv3 = __int_as_float(c3.z);

        accU.x = fmaf(d0.x * sv0, w0.x, accU.x); accU.y = fmaf(d0.y * sv0, w0.y, accU.y);
        accU.z = fmaf(d0.z * sv0, w0.z, accU.z); accU.w = fmaf(d0.w * sv0, w0.w, accU.w);
        accU.x = fmaf(d1.x * sv1, w1.x, accU.x); accU.y = fmaf(d1.y * sv1, w1.y, accU.y);
        accU.z = fmaf(d1.z * sv1, w1.z, accU.z); accU.w = fmaf(d1.w * sv1, w1.w, accU.w);
        accU.x = fmaf(d2.x * sv2, w2.x, accU.x); accU.y = fmaf(d2.y * sv2, w2.y, accU.y);
        accU.z = fmaf(d2.z * sv2, w2.z, accU.z); accU.w = fmaf(d2.w * sv2, w2.w, accU.w);
        accU.x = fmaf(d3.x * sv3, w3.x, accU.x); accU.y = fmaf(d3.y * sv3, w3.y, accU.y);
        accU.z = fmaf(d3.z * sv3, w3.z, accU.z); accU.w = fmaf(d3.w * sv3, w3.w, accU.w);

        accSe.x += w0.x + w1.x + w2.x + w3.x;
        accSe.y += w0.y + w1.y + w2.y + w3.y;
        accSe.z += w0.z + w1.z + w2.z + w3.z;
        accSe.w += w0.w + w1.w + w2.w + w3.w;

        red4(&aggD[c0.y * 16 + q], ssu.x * w0.x, ssu.y * w0.y, ssu.z * w0.z, ssu.w * w0.w);
        red4(&aggD[c1.y * 16 + q], ssu.x * w1.x, ssu.y * w1.y, ssu.z * w1.z, ssu.w * w1.w);
        red4(&aggD[c2.y * 16 + q], ssu.x * w2.x, ssu.y * w2.y, ssu.z * w2.z, ssu.w * w2.w);
        red4(&aggD[c3.y * 16 + q], ssu.x * w3.x, ssu.y * w3.y, ssu.z * w3.z, ssu.w * w3.w);
        red4(&de[c0.y * 16 + q], w0.x, w0.y, w0.z, w0.w);
        red4(&de[c1.y * 16 + q], w1.x, w1.y, w1.z, w1.w);
        red4(&de[c2.y * 16 + q], w2.x, w2.y, w2.z, w2.w);
        red4(&de[c3.y * 16 + q], w3.x, w3.y, w3.z, w3.w);
    }
    for (; i < end; i++) {
        int4 c = __ldg(g_csrV + i);
        float sv = __int_as_float(c.z);
        float4 w = __ldcs((const float4*)ew + (size_t)c.x * 16 + q);
        float4 d = __ldg((const float4*)g_dst + c.y * 16 + q);
        accU.x = fmaf(d.x * sv, w.x, accU.x); accU.y = fmaf(d.y * sv, w.y, accU.y);
        accU.z = fmaf(d.z * sv, w.z, accU.z); accU.w = fmaf(d.w * sv, w.w, accU.w);
        accSe.x += w.x; accSe.y += w.y; accSe.z += w.z; accSe.w += w.w;
        red4(&aggD[c.y * 16 + q], ssu.x * w.x, ssu.y * w.y, ssu.z * w.z, ssu.w * w.w);
        red4(&de[c.y * 16 + q], w.x, w.y, w.z, w.w);
    }
    accU.x *= B_SC; accU.y *= B_SC; accU.z *= B_SC; accU.w *= B_SC;
    ((float4*)(g_zbuf + ZB_AGGU + (size_t)t * NUD))[u * 16 + q] = accU;
    ((float4*)(g_zbuf + ZB_SE   + (size_t)t * NUD))[u * 16 + q] = accSe;  // raw
}

// ---------------- layer-1 edge pass (weights inline, unroll-4) ----------------
__global__ void __launch_bounds__(256) gath1_k(int t) {
    int gid = blockIdx.x * 256 + threadIdx.x;
    int u = gid >> 4, q = gid & 15;
    if (u >= NUc) return;
    int si = t * NUc + u;
    float su = g_isqU[si];
    float du = g_dU[si];
    float4 s = ((const float4*)g_src)[u * 16 + q];
    float4 ssu = make_float4(s.x * su, s.y * su, s.z * su, s.w * su);
    float4 sw = ((const float4*)g_seW)[(size_t)t * NUc * 16 + u * 16 + q];
    int beg = g_start[si];
    int end = (si + 1 < SCAN_N) ? g_start[si + 1] : ETOT_E;

    float4 accU = make_float4(0.f, 0.f, 0.f, 0.f);
    float4* aggD = (float4*)(g_zbuf + ZB_AGGD + (size_t)t * NID);
    const float4* deW = (const float4*)g_deW + (size_t)t * NIc * 16;

    int i = beg;
#pragma unroll 1
    for (; i + 4 <= end; i += 4) {
        int4 c0 = __ldg(g_csrV + i + 0);
        int4 c1 = __ldg(g_csrV + i + 1);
        int4 c2 = __ldg(g_csrV + i + 2);
        int4 c3 = __ldg(g_csrV + i + 3);
        float4 e0 = __ldg(deW + c0.y * 16 + q);
        float4 e1 = __ldg(deW + c1.y * 16 + q);
        float4 e2 = __ldg(deW + c2.y * 16 + q);
        float4 e3 = __ldg(deW + c3.y * 16 + q);
        float4 d0 = __ldg((const float4*)g_dst + c0.y * 16 + q);
        float4 d1 = __ldg((const float4*)g_dst + c1.y * 16 + q);
        float4 d2 = __ldg((const float4*)g_dst + c2.y * 16 + q);
        float4 d3 = __ldg((const float4*)g_dst + c3.y * 16 + q);
#pragma unroll
        for (int j = 0; j < 4; j++) {
            int4 c = j == 0 ? c0 : (j == 1 ? c1 : (j == 2 ? c2 : c3));
            float4 dw = j == 0 ? e0 : (j == 1 ? e1 : (j == 2 ? e2 : e3));
            float4 d  = j == 0 ? d0 : (j == 1 ? d1 : (j == 2 ? d2 : d3));
            float sv = __int_as_float(c.z);
            float r = 1.0f / (du + __int_as_float(c.w));
            float4 w;
            w.x = lrelu((sw.x + dw.x) * r);
            w.y = lrelu((sw.y + dw.y) * r);
            w.z = lrelu((sw.z + dw.z) * r);
            w.w = lrelu((sw.w + dw.w) * r);
            accU.x = fmaf(d.x * sv, w.x, accU.x);
            accU.y = fmaf(d.y * sv, w.y, accU.y);
            accU.z = fmaf(d.z * sv, w.z, accU.z);
            accU.w = fmaf(d.w * sv, w.w, accU.w);
            red4(&aggD[c.y * 16 + q], ssu.x * w.x, ssu.y * w.y, ssu.z * w.z, ssu.w * w.w);
        }
    }
    for (; i < end; i++) {
        int4 c = __ldg(g_csrV + i);
        float sv = __int_as_float(c.z);
        float r = 1.0f / (du + __int_as_float(c.w));
        float4 dw = __ldg(deW + c.y * 16 + q);
        float4 w;
        w.x = lrelu((sw.x + dw.x) * r);
        w.y = lrelu((sw.y + dw.y) * r);
        w.z = lrelu((sw.z + dw.z) * r);
        w.w = lrelu((sw.w + dw.w) * r);
        float4 d = __ldg((const float4*)g_dst + c.y * 16 + q);
        accU.x = fmaf(d.x * sv, w.x, accU.x);
        accU.y = fmaf(d.y * sv, w.y, accU.y);
        accU.z = fmaf(d.z * sv, w.z, accU.z);
        accU.w = fmaf(d.w * sv, w.w, accU.w);
        red4(&aggD[c.y * 16 + q], ssu.x * w.x, ssu.y * w.y, ssu.z * w.z, ssu.w * w.w);
    }
    ((float4*)(g_zbuf + ZB_AGGU + (size_t)t * NUD))[u * 16 + q] = accU;
}

// ---------------- node kernels ----------------

__global__ void nodeCombine_k(const float* __restrict__ W, int items) {
    __shared__ float Ws[64 * 64];
    __shared__ float R[4][3][64];
    int tx = threadIdx.x, ty = threadIdx.y;
    int lin = ty * 64 + tx;
#pragma unroll
    for (int i = 0; i < 16; i++) Ws[lin + 256 * i] = W[lin + 256 * i];

    int N = items ? NIc : NUc;
    int nd = items ? NID : NUD;
    int n = blockIdx.x * 4 + ty;
    const float* agg = items ? (g_zbuf + ZB_AGGD) : (g_zbuf + ZB_AGGU);
    if (n < N) {
        R[ty][0][tx] = agg[(size_t)0 * nd + n * 64 + tx];
        R[ty][1][tx] = agg[(size_t)1 * nd + n * 64 + tx];
        R[ty][2][tx] = agg[(size_t)2 * nd + n * 64 + tx];
    }
    __syncthreads();
    if (n >= N) return;

    float s0 = 0.f, s1 = 0.f, s2 = 0.f;
#pragma unroll
    for (int k = 0; k < 64; k++) {
        float wk = Ws[k * 64 + tx];
        s0 = fmaf(R[ty][0][k], wk, s0);
        s1 = fmaf(R[ty][1][k], wk, s1);
        s2 = fmaf(R[ty][2][k], wk, s2);
    }
    const float* isq = items ? g_isqV : g_isqU;
    int NN = items ? NIc : NUc;
    float o = lrelu(s0 * isq[0 * NN + n]) + 0.5f * lrelu(s1 * isq[1 * NN + n])
            + 0.25f * lrelu(s2 * isq[2 * NN + n]);
    float* cur = items ? g_dst : g_src;
    float* acc = items ? g_dstAll : g_srcAll;
    cur[n * 64 + tx] = o;
    acc[n * 64 + tx] += o;
}

// seW_t = (se_raw * B_SC) @ We  — B_SC folded into the weight tile
__global__ void seGemm_k(const float* __restrict__ W, int t, int items) {
    __shared__ float Ws[64 * 64];
    __shared__ float R[4][64];
    int tx = threadIdx.x, ty = threadIdx.y;
    int lin = ty * 64 + tx;
#pragma unroll
    for (int i = 0; i < 16; i++) Ws[lin + 256 * i] = W[lin + 256 * i] * B_SC;

    int N = items ? NIc : NUc;
    const float* in  = items ? (g_zbuf + ZB_DE + (size_t)t * NID)
                             : (g_zbuf + ZB_SE + (size_t)t * NUD);
    float* out = items ? (g_deW + (size_t)t * NID) : (g_seW + (size_t)t * NUD);
    int n = blockIdx.x * 4 + ty;
    if (n < N) R[ty][tx] = in[n * 64 + tx];
    __syncthreads();
    if (n >= N) return;

    float s = 0.f;
#pragma unroll
    for (int k = 0; k < 64; k++) s = fmaf(R[ty][k], Ws[k * 64 + tx], s);
    out[n * 64 + tx] = s;
}

__global__ void writeOut_k(float* __restrict__ out) {
    int i = blockIdx.x * blockDim.x + threadIdx.x;
    if (i < NUD) out[i] = g_srcAll[i] / 3.0f;
    else if (i < NUD + NID) out[i] = g_dstAll[i - NUD] / 3.0f;
}

// ---------------- launch ----------------
extern "C" void kernel_launch(void* const* d_in, const int* in_sizes, int n_in,
                              void* d_out, int out_size) {
    const float* user  = (const float*)d_in[0];
    const float* item  = (const float*)d_in[1];
    const float* ebuy  = (const float*)d_in[2];
    const float* ecart = (const float*)d_in[3];
    const float* epv   = (const float*)d_in[4];
    const float* nodeW = (const float*)d_in[5];
    const float* edgeW = (const float*)d_in[6];
    const int* bu = (const int*)d_in[7];
    const int* bv = (const int*)d_in[8];
    const int* cu = (const int*)d_in[9];
    const int* cv = (const int*)d_in[10];
    const int* pu = (const int*)d_in[11];
    const int* pvv = (const int*)d_in[12];
    float* out = (float*)d_out;

    const int TB = 256;
    auto nb = [](long long n, int tb) { return (unsigned)((n + tb - 1) / tb); };

    // degrees
    zeroDeg_k<<<nb(SCAN_ALL, TB), TB>>>();
    degCount_k<<<nb(EBc, TB), TB>>>(0, bu, bv, EBc);
    degCount_k<<<nb(ECc, TB), TB>>>(1, cu, cv, ECc);
    degCount_k<<<nb(EPc, TB), TB>>>(2, pu, pvv, EPc);
    degConv_k<<<nb(SCAN_ALL, TB), TB>>>();

    // u-side CSR with packed payload (needs isqV/dV -> after degConv)
    blockScan_k<<<NBLK_SCAN, 1024>>>();
    scanSums_k<<<1, 512>>>();
    addOff_k<<<NBLK_SCAN, 1024>>>();
    csrFill_k<<<nb(EBc, TB), TB>>>(0, bu, bv, EBc);
    csrFill_k<<<nb(ECc, TB), TB>>>(1, cu, cv, ECc);
    csrFill_k<<<nb(EPc, TB), TB>>>(2, pu, pvv, EPc);

    scaleInit_k<<<nb(NUD, TB), TB>>>(user, 0);
    scaleInit_k<<<nb(NID, TB), TB>>>(item, 1);

    dim3 bt(64, 4);
    unsigned gU = nb((long long)NUc * 16, 256);

    // -------- layer 0: zero v-side RED targets (aggD + de) --------
    zeroRange_k<<<nb((long long)(3 * NID) / 4, TB), TB>>>(ZB_AGGD / 4, (size_t)3 * NID / 4);
    zeroRange_k<<<nb((long long)(3 * NID) / 4, TB), TB>>>(ZB_DE / 4, (size_t)3 * NID / 4);

    gath0_k<<<gU, 256>>>(ebuy, 0, 0);
    gath0_k<<<gU, 256>>>(ecart, 1, 0);
    gath0_k<<<gU, 256>>>(epv, 2, 0);

    nodeCombine_k<<<nb(NIc, 4), bt>>>(nodeW, 1);
    nodeCombine_k<<<nb(NUc, 4), bt>>>(nodeW, 0);

    for (int t = 0; t < 3; t++) {
        seGemm_k<<<nb(NUc, 4), bt>>>(edgeW, t, 0);
        seGemm_k<<<nb(NIc, 4), bt>>>(edgeW, t, 1);
    }

    // -------- layer 1 --------
    zeroRange_k<<<nb((long long)(3 * NID) / 4, TB), TB>>>(ZB_AGGD / 4, (size_t)3 * NID / 4);

    gath1_k<<<gU, 256>>>(0);
    gath1_k<<<gU, 256>>>(1);
    gath1_k<<<gU, 256>>>(2);

    nodeCombine_k<<<nb(NIc, 4), bt>>>(nodeW + Dc * Dc, 1);
    nodeCombine_k<<<nb(NUc, 4), bt>>>(nodeW + Dc * Dc, 0);

    writeOut_k<<<nb(NUD + NID, TB), TB>>>(out);
}

// round 9
// speedup vs baseline: 1.2186x; 1.0225x over previous
#include <cuda_runtime.h>

// ---------------- problem constants ----------------
constexpr int NUc = 100000;
constexpr int NIc = 50000;
constexpr int Dc  = 64;
constexpr int EBc = 500000;
constexpr int ECc = 1000000;
constexpr int EPc = 2000000;
constexpr int ETOT_E = EBc + ECc + EPc;   // 3.5M

constexpr int NUD = NUc * Dc;  // 6.4M
constexpr int NID = NIc * Dc;  // 3.2M

constexpr float A_SC = 0.0045f;
constexpr float B_SC = 0.0045f;

// zbuf layout: aggU[3][NUD] | aggD[3][NID] | se[3][NUD] | de[3][NID]
constexpr size_t ZB_AGGU = 0;
constexpr size_t ZB_AGGD = (size_t)3 * NUD;
constexpr size_t ZB_SE   = ZB_AGGD + (size_t)3 * NID;
constexpr size_t ZB_DE   = ZB_SE + (size_t)3 * NUD;
constexpr size_t ZTOT    = ZB_DE + (size_t)3 * NID;

constexpr int SCAN_ALL  = 3 * (NUc + NIc);           // all degree slots (users first)
constexpr int SCAN_N    = 3 * NUc;                   // scan domain (user lists only)
constexpr int NBLK_SCAN = (SCAN_N + 1023) / 1024;    // 293

// ---------------- device scratch (no allocation allowed) ----------------
__device__ float g_zbuf[ZTOT];
__device__ float g_seW[(size_t)3 * NUD];
__device__ float g_deW[(size_t)3 * NID];
__device__ float g_src[NUD];
__device__ float g_dst[NID];
__device__ float g_srcAll[NUD];
__device__ float g_dstAll[NID];
__device__ int   g_deg[SCAN_ALL];
__device__ float g_isqU[3 * NUc];
__device__ float g_isqV[3 * NIc];
__device__ float g_dU[3 * NUc];
__device__ float g_dV[3 * NIc];
// u-side CSR with pre-joined payload: {e, v, bits(isqV[v]), bits(dV[v])}
__device__ int4 g_csrV[ETOT_E];
__device__ int g_tmpScan[SCAN_N];
__device__ int g_blkSum[512];
__device__ int g_blkSumScan[512];
__device__ int g_start[SCAN_N];
__device__ int g_cur[SCAN_N];

__device__ __forceinline__ float lrelu(float x) { return x >= 0.0f ? x : 0.01f * x; }

// NOTE: no "memory" clobber — RED targets are never read in-kernel; this lets
// the compiler pipeline subsequent loads above the reductions.
__device__ __forceinline__ void red4(float4* a, float x, float y, float z, float w) {
    asm volatile("red.global.add.v4.f32 [%0], {%1, %2, %3, %4};"
                 :: "l"(a), "f"(x), "f"(y), "f"(z), "f"(w));
}

// ---------------- setup kernels ----------------

__global__ void zeroRange_k(size_t off4, size_t n4) {
    size_t i = (size_t)blockIdx.x * blockDim.x + threadIdx.x;
    if (i < n4) ((float4*)g_zbuf)[off4 + i] = make_float4(0.f, 0.f, 0.f, 0.f);
}

__global__ void zeroDeg_k() {
    int i = blockIdx.x * blockDim.x + threadIdx.x;
    if (i < SCAN_ALL) g_deg[i] = 0;
}

__global__ void degCount_k(int t, const int* __restrict__ U, const int* __restrict__ V, int E) {
    int e = blockIdx.x * blockDim.x + threadIdx.x;
    if (e >= E) return;
    atomicAdd(&g_deg[t * NUc + U[e]], 1);
    atomicAdd(&g_deg[3 * NUc + t * NIc + V[e]], 1);
}

__global__ void degConv_k() {
    int i = blockIdx.x * blockDim.x + threadIdx.x;
    if (i < 3 * NUc) {
        float f = (float)max(g_deg[i], 1);
        g_dU[i] = f;
        g_isqU[i] = rsqrtf(f);
    } else if (i < SCAN_ALL) {
        int j = i - 3 * NUc;
        float f = (float)max(g_deg[i], 1);
        g_dV[j] = f;
        g_isqV[j] = rsqrtf(f);
    }
}

// ---- hierarchical exclusive scan of user-side degrees ----
__global__ void blockScan_k() {
    __shared__ int wsum[32];
    int tid = threadIdx.x;
    int gi = blockIdx.x * 1024 + tid;
    int d = (gi < SCAN_N) ? g_deg[gi] : 0;
    int x = d;
#pragma unroll
    for (int o = 1; o < 32; o <<= 1) {
        int y = __shfl_up_sync(0xFFFFFFFFu, x, o);
        if ((tid & 31) >= o) x += y;
    }
    if ((tid & 31) == 31) wsum[tid >> 5] = x;
    __syncthreads();
    if (tid < 32) {
        int w = wsum[tid];
#pragma unroll
        for (int o = 1; o < 32; o <<= 1) {
            int y = __shfl_up_sync(0xFFFFFFFFu, w, o);
            if (tid >= o) w += y;
        }
        wsum[tid] = w;
    }
    __syncthreads();
    int incl = x + ((tid >= 32) ? wsum[(tid >> 5) - 1] : 0);
    if (gi < SCAN_N) g_tmpScan[gi] = incl - d;
    if (tid == 1023) g_blkSum[blockIdx.x] = incl;
}

__global__ void scanSums_k() {
    __shared__ int wsum[32];
    int tid = threadIdx.x;   // 512 threads, NBLK_SCAN <= 512
    int d = (tid < NBLK_SCAN) ? g_blkSum[tid] : 0;
    int x = d;
#pragma unroll
    for (int o = 1; o < 32; o <<= 1) {
        int y = __shfl_up_sync(0xFFFFFFFFu, x, o);
        if ((tid & 31) >= o) x += y;
    }
    if ((tid & 31) == 31) wsum[tid >> 5] = x;
    __syncthreads();
    if (tid < 32) {
        int w = (tid < 16) ? wsum[tid] : 0;
#pragma unroll
        for (int o = 1; o < 32; o <<= 1) {
            int y = __shfl_up_sync(0xFFFFFFFFu, w, o);
            if (tid >= o) w += y;
        }
        wsum[tid] = w;
    }
    __syncthreads();
    int incl = x + ((tid >= 32) ? wsum[(tid >> 5) - 1] : 0);
    if (tid < NBLK_SCAN) g_blkSumScan[tid] = incl;
}

__global__ void addOff_k() {
    int gi = blockIdx.x * 1024 + threadIdx.x;
    if (gi >= SCAN_N) return;
    int blk = gi >> 10;
    int s = g_tmpScan[gi] + (blk ? g_blkSumScan[blk - 1] : 0);
    g_start[gi] = s;
    g_cur[gi] = s;
}

// pack {e, v, isqV[v], dV[v]} so gather loops have a depth-2 load chain
__global__ void csrFill_k(int t, const int* __restrict__ U, const int* __restrict__ V, int E) {
    int e = blockIdx.x * blockDim.x + threadIdx.x;
    if (e >= E) return;
    int u = U[e], v = V[e];
    int p = atomicAdd(&g_cur[t * NUc + u], 1);
    g_csrV[p] = make_int4(e, v, __float_as_int(g_isqV[t * NIc + v]),
                          __float_as_int(g_dV[t * NIc + v]));
}

__global__ void scaleInit_k(const float* __restrict__ emb, int items) {
    int i = blockIdx.x * blockDim.x + threadIdx.x;
    int n = items ? NID : NUD;
    if (i >= n) return;
    float v = emb[i] * A_SC;
    if (items) { g_dst[i] = v; g_dstAll[i] = v; }
    else       { g_src[i] = v; g_srcAll[i] = v; }
}

// ---------------- layer-0 edge pass: one u per WARP, 4 edges/warp-iter ----------------
// Half-warp sub=0 handles edges i, i+2; sub=1 handles i+1, i+3 (same u => no
// divergence). regs accumulate aggU/se (shfl-combined across halves at the end);
// REDs scatter aggD and de.
__global__ void __launch_bounds__(256) gath0_k(const float* __restrict__ ew, int t) {
    int u = (blockIdx.x * 256 + threadIdx.x) >> 5;
    if (u >= NUc) return;
    int lane = threadIdx.x & 31;
    int sub = lane >> 4;
    int q = lane & 15;

    int si = t * NUc + u;
    float su = g_isqU[si] * B_SC;
    float4 s = ((const float4*)g_src)[u * 16 + q];
    float4 ssu = make_float4(s.x * su, s.y * su, s.z * su, s.w * su);
    int beg = g_start[si];
    int end = (si + 1 < SCAN_N) ? g_start[si + 1] : ETOT_E;

    float4 accU = make_float4(0.f, 0.f, 0.f, 0.f);
    float4 accSe = make_float4(0.f, 0.f, 0.f, 0.f);
    float4* aggD = (float4*)(g_zbuf + ZB_AGGD + (size_t)t * NID);
    float4* de   = (float4*)(g_zbuf + ZB_DE   + (size_t)t * NID);

    int i = beg;
    for (; i + 4 <= end; i += 4) {
        int4 c0 = __ldg(g_csrV + i + sub);
        int4 c1 = __ldg(g_csrV + i + 2 + sub);
        float4 w0 = __ldcs((const float4*)ew + (size_t)c0.x * 16 + q);
        float4 w1 = __ldcs((const float4*)ew + (size_t)c1.x * 16 + q);
        float4 d0 = __ldg((const float4*)g_dst + c0.y * 16 + q);
        float4 d1 = __ldg((const float4*)g_dst + c1.y * 16 + q);
        float sv0 = __int_as_float(c0.z), sv1 = __int_as_float(c1.z);

        accU.x = fmaf(d0.x * sv0, w0.x, accU.x); accU.y = fmaf(d0.y * sv0, w0.y, accU.y);
        accU.z = fmaf(d0.z * sv0, w0.z, accU.z); accU.w = fmaf(d0.w * sv0, w0.w, accU.w);
        accU.x = fmaf(d1.x * sv1, w1.x, accU.x); accU.y = fmaf(d1.y * sv1, w1.y, accU.y);
        accU.z = fmaf(d1.z * sv1, w1.z, accU.z); accU.w = fmaf(d1.w * sv1, w1.w, accU.w);
        accSe.x += w0.x + w1.x; accSe.y += w0.y + w1.y;
        accSe.z += w0.z + w1.z; accSe.w += w0.w + w1.w;

        red4(&aggD[c0.y * 16 + q], ssu.x * w0.x, ssu.y * w0.y, ssu.z * w0.z, ssu.w * w0.w);
        red4(&aggD[c1.y * 16 + q], ssu.x * w1.x, ssu.y * w1.y, ssu.z * w1.z, ssu.w * w1.w);
        red4(&de[c0.y * 16 + q], w0.x, w0.y, w0.z, w0.w);
        red4(&de[c1.y * 16 + q], w1.x, w1.y, w1.z, w1.w);
    }
    for (; i < end; i += 2) {
        int idx = i + sub;
        if (idx < end) {
            int4 c = __ldg(g_csrV + idx);
            float sv = __int_as_float(c.z);
            float4 w = __ldcs((const float4*)ew + (size_t)c.x * 16 + q);
            float4 d = __ldg((const float4*)g_dst + c.y * 16 + q);
            accU.x = fmaf(d.x * sv, w.x, accU.x); accU.y = fmaf(d.y * sv, w.y, accU.y);
            accU.z = fmaf(d.z * sv, w.z, accU.z); accU.w = fmaf(d.w * sv, w.w, accU.w);
            accSe.x += w.x; accSe.y += w.y; accSe.z += w.z; accSe.w += w.w;
            red4(&aggD[c.y * 16 + q], ssu.x * w.x, ssu.y * w.y, ssu.z * w.z, ssu.w * w.w);
            red4(&de[c.y * 16 + q], w.x, w.y, w.z, w.w);
        }
    }
    // combine the two half-warp partials (same u, same q)
    accU.x += __shfl_down_sync(0xFFFFFFFFu, accU.x, 16);
    accU.y += __shfl_down_sync(0xFFFFFFFFu, accU.y, 16);
    accU.z += __shfl_down_sync(0xFFFFFFFFu, accU.z, 16);
    accU.w += __shfl_down_sync(0xFFFFFFFFu, accU.w, 16);
    accSe.x += __shfl_down_sync(0xFFFFFFFFu, accSe.x, 16);
    accSe.y += __shfl_down_sync(0xFFFFFFFFu, accSe.y, 16);
    accSe.z += __shfl_down_sync(0xFFFFFFFFu, accSe.z, 16);
    accSe.w += __shfl_down_sync(0xFFFFFFFFu, accSe.w, 16);
    if (sub == 0) {
        accU.x *= B_SC; accU.y *= B_SC; accU.z *= B_SC; accU.w *= B_SC;
        ((float4*)(g_zbuf + ZB_AGGU + (size_t)t * NUD))[u * 16 + q] = accU;
        ((float4*)(g_zbuf + ZB_SE   + (size_t)t * NUD))[u * 16 + q] = accSe;  // raw
    }
}

// ---------------- layer-1 edge pass: weights inline, one u per warp ----------------
__global__ void __launch_bounds__(256) gath1_k(int t) {
    int u = (blockIdx.x * 256 + threadIdx.x) >> 5;
    if (u >= NUc) return;
    int lane = threadIdx.x & 31;
    int sub = lane >> 4;
    int q = lane & 15;

    int si = t * NUc + u;
    float su = g_isqU[si];
    float du = g_dU[si];
    float4 s = ((const float4*)g_src)[u * 16 + q];
    float4 ssu = make_float4(s.x * su, s.y * su, s.z * su, s.w * su);
    float4 sw = ((const float4*)g_seW)[(size_t)t * NUc * 16 + u * 16 + q];
    int beg = g_start[si];
    int end = (si + 1 < SCAN_N) ? g_start[si + 1] : ETOT_E;

    float4 accU = make_float4(0.f, 0.f, 0.f, 0.f);
    float4* aggD = (float4*)(g_zbuf + ZB_AGGD + (size_t)t * NID);
    const float4* deW = (const float4*)g_deW + (size_t)t * NIc * 16;

    int i = beg;
    for (; i + 4 <= end; i += 4) {
        int4 c0 = __ldg(g_csrV + i + sub);
        int4 c1 = __ldg(g_csrV + i + 2 + sub);
        float4 e0 = __ldg(deW + c0.y * 16 + q);
        float4 e1 = __ldg(deW + c1.y * 16 + q);
        float4 d0 = __ldg((const float4*)g_dst + c0.y * 16 + q);
        float4 d1 = __ldg((const float4*)g_dst + c1.y * 16 + q);
        {
            float sv = __int_as_float(c0.z);
            float r = 1.0f / (du + __int_as_float(c0.w));
            float4 w;
            w.x = lrelu((sw.x + e0.x) * r); w.y = lrelu((sw.y + e0.y) * r);
            w.z = lrelu((sw.z + e0.z) * r); w.w = lrelu((sw.w + e0.w) * r);
            accU.x = fmaf(d0.x * sv, w.x, accU.x); accU.y = fmaf(d0.y * sv, w.y, accU.y);
            accU.z = fmaf(d0.z * sv, w.z, accU.z); accU.w = fmaf(d0.w * sv, w.w, accU.w);
            red4(&aggD[c0.y * 16 + q], ssu.x * w.x, ssu.y * w.y, ssu.z * w.z, ssu.w * w.w);
        }
        {
            float sv = __int_as_float(c1.z);
            float r = 1.0f / (du + __int_as_float(c1.w));
            float4 w;
            w.x = lrelu((sw.x + e1.x) * r); w.y = lrelu((sw.y + e1.y) * r);
            w.z = lrelu((sw.z + e1.z) * r); w.w = lrelu((sw.w + e1.w) * r);
            accU.x = fmaf(d1.x * sv, w.x, accU.x); accU.y = fmaf(d1.y * sv, w.y, accU.y);
            accU.z = fmaf(d1.z * sv, w.z, accU.z); accU.w = fmaf(d1.w * sv, w.w, accU.w);
            red4(&aggD[c1.y * 16 + q], ssu.x * w.x, ssu.y * w.y, ssu.z * w.z, ssu.w * w.w);
        }
    }
    for (; i < end; i += 2) {
        int idx = i + sub;
        if (idx < end) {
            int4 c = __ldg(g_csrV + idx);
            float sv = __int_as_float(c.z);
            float r = 1.0f / (du + __int_as_float(c.w));
            float4 dw = __ldg(deW + c.y * 16 + q);
            float4 w;
            w.x = lrelu((sw.x + dw.x) * r); w.y = lrelu((sw.y + dw.y) * r);
            w.z = lrelu((sw.z + dw.z) * r); w.w = lrelu((sw.w + dw.w) * r);
            float4 d = __ldg((const float4*)g_dst + c.y * 16 + q);
            accU.x = fmaf(d.x * sv, w.x, accU.x); accU.y = fmaf(d.y * sv, w.y, accU.y);
            accU.z = fmaf(d.z * sv, w.z, accU.z); accU.w = fmaf(d.w * sv, w.w, accU.w);
            red4(&aggD[c.y * 16 + q], ssu.x * w.x, ssu.y * w.y, ssu.z * w.z, ssu.w * w.w);
        }
    }
    accU.x += __shfl_down_sync(0xFFFFFFFFu, accU.x, 16);
    accU.y += __shfl_down_sync(0xFFFFFFFFu, accU.y, 16);
    accU.z += __shfl_down_sync(0xFFFFFFFFu, accU.z, 16);
    accU.w += __shfl_down_sync(0xFFFFFFFFu, accU.w, 16);
    if (sub == 0) {
        ((float4*)(g_zbuf + ZB_AGGU + (size_t)t * NUD))[u * 16 + q] = accU;
    }
}

// ---------------- node kernels ----------------

__global__ void nodeCombine_k(const float* __restrict__ W, int items) {
    __shared__ float Ws[64 * 64];
    __shared__ float R[4][3][64];
    int tx = threadIdx.x, ty = threadIdx.y;
    int lin = ty * 64 + tx;
#pragma unroll
    for (int i = 0; i < 16; i++) Ws[lin + 256 * i] = W[lin + 256 * i];

    int N = items ? NIc : NUc;
    int nd = items ? NID : NUD;
    int n = blockIdx.x * 4 + ty;
    const float* agg = items ? (g_zbuf + ZB_AGGD) : (g_zbuf + ZB_AGGU);
    if (n < N) {
        R[ty][0][tx] = agg[(size_t)0 * nd + n * 64 + tx];
        R[ty][1][tx] = agg[(size_t)1 * nd + n * 64 + tx];
        R[ty][2][tx] = agg[(size_t)2 * nd + n * 64 + tx];
    }
    __syncthreads();
    if (n >= N) return;

    float s0 = 0.f, s1 = 0.f, s2 = 0.f;
#pragma unroll
    for (int k = 0; k < 64; k++) {
        float wk = Ws[k * 64 + tx];
        s0 = fmaf(R[ty][0][k], wk, s0);
        s1 = fmaf(R[ty][1][k], wk, s1);
        s2 = fmaf(R[ty][2][k], wk, s2);
    }
    const float* isq = items ? g_isqV : g_isqU;
    int NN = items ? NIc : NUc;
    float o = lrelu(s0 * isq[0 * NN + n]) + 0.5f * lrelu(s1 * isq[1 * NN + n])
            + 0.25f * lrelu(s2 * isq[2 * NN + n]);
    float* cur = items ? g_dst : g_src;
    float* acc = items ? g_dstAll : g_srcAll;
    cur[n * 64 + tx] = o;
    acc[n * 64 + tx] += o;
}

// seW_t = (se_raw * B_SC) @ We  — B_SC folded into the weight tile
__global__ void seGemm_k(const float* __restrict__ W, int t, int items) {
    __shared__ float Ws[64 * 64];
    __shared__ float R[4][64];
    int tx = threadIdx.x, ty = threadIdx.y;
    int lin = ty * 64 + tx;
#pragma unroll
    for (int i = 0; i < 16; i++) Ws[lin + 256 * i] = W[lin + 256 * i] * B_SC;

    int N = items ? NIc : NUc;
    const float* in  = items ? (g_zbuf + ZB_DE + (size_t)t * NID)
                             : (g_zbuf + ZB_SE + (size_t)t * NUD);
    float* out = items ? (g_deW + (size_t)t * NID) : (g_seW + (size_t)t * NUD);
    int n = blockIdx.x * 4 + ty;
    if (n < N) R[ty][tx] = in[n * 64 + tx];
    __syncthreads();
    if (n >= N) return;

    float s = 0.f;
#pragma unroll
    for (int k = 0; k < 64; k++) s = fmaf(R[ty][k], Ws[k * 64 + tx], s);
    out[n * 64 + tx] = s;
}

__global__ void writeOut_k(float* __restrict__ out) {
    int i = blockIdx.x * blockDim.x + threadIdx.x;
    if (i < NUD) out[i] = g_srcAll[i] / 3.0f;
    else if (i < NUD + NID) out[i] = g_dstAll[i - NUD] / 3.0f;
}

// ---------------- launch ----------------
extern "C" void kernel_launch(void* const* d_in, const int* in_sizes, int n_in,
                              void* d_out, int out_size) {
    const float* user  = (const float*)d_in[0];
    const float* item  = (const float*)d_in[1];
    const float* ebuy  = (const float*)d_in[2];
    const float* ecart = (const float*)d_in[3];
    const float* epv   = (const float*)d_in[4];
    const float* nodeW = (const float*)d_in[5];
    const float* edgeW = (const float*)d_in[6];
    const int* bu = (const int*)d_in[7];
    const int* bv = (const int*)d_in[8];
    const int* cu = (const int*)d_in[9];
    const int* cv = (const int*)d_in[10];
    const int* pu = (const int*)d_in[11];
    const int* pvv = (const int*)d_in[12];
    float* out = (float*)d_out;

    const int TB = 256;
    auto nb = [](long long n, int tb) { return (unsigned)((n + tb - 1) / tb); };

    // degrees
    zeroDeg_k<<<nb(SCAN_ALL, TB), TB>>>();
    degCount_k<<<nb(EBc, TB), TB>>>(0, bu, bv, EBc);
    degCount_k<<<nb(ECc, TB), TB>>>(1, cu, cv, ECc);
    degCount_k<<<nb(EPc, TB), TB>>>(2, pu, pvv, EPc);
    degConv_k<<<nb(SCAN_ALL, TB), TB>>>();

    // u-side CSR with packed payload (needs isqV/dV -> after degConv)
    blockScan_k<<<NBLK_SCAN, 1024>>>();
    scanSums_k<<<1, 512>>>();
    addOff_k<<<NBLK_SCAN, 1024>>>();
    csrFill_k<<<nb(EBc, TB), TB>>>(0, bu, bv, EBc);
    csrFill_k<<<nb(ECc, TB), TB>>>(1, cu, cv, ECc);
    csrFill_k<<<nb(EPc, TB), TB>>>(2, pu, pvv, EPc);

    scaleInit_k<<<nb(NUD, TB), TB>>>(user, 0);
    scaleInit_k<<<nb(NID, TB), TB>>>(item, 1);

    dim3 bt(64, 4);
    unsigned gW = nb((long long)NUc * 32, 256);   // one warp per u

    // -------- layer 0: zero v-side RED targets (aggD + de) --------
    zeroRange_k<<<nb((long long)(3 * NID) / 4, TB), TB>>>(ZB_AGGD / 4, (size_t)3 * NID / 4);
    zeroRange_k<<<nb((long long)(3 * NID) / 4, TB), TB>>>(ZB_DE / 4, (size_t)3 * NID / 4);

    gath0_k<<<gW, 256>>>(ebuy, 0);
    gath0_k<<<gW, 256>>>(ecart, 1);
    gath0_k<<<gW, 256>>>(epv, 2);

    nodeCombine_k<<<nb(NIc, 4), bt>>>(nodeW, 1);
    nodeCombine_k<<<nb(NUc, 4), bt>>>(nodeW, 0);

    for (int t = 0; t < 3; t++) {
        seGemm_k<<<nb(NUc, 4), bt>>>(edgeW, t, 0);
        seGemm_k<<<nb(NIc, 4), bt>>>(edgeW, t, 1);
    }

    // -------- layer 1 --------
    zeroRange_k<<<nb((long long)(3 * NID) / 4, TB), TB>>>(ZB_AGGD / 4, (size_t)3 * NID / 4);

    gath1_k<<<gW, 256>>>(0);
    gath1_k<<<gW, 256>>>(1);
    gath1_k<<<gW, 256>>>(2);

    nodeCombine_k<<<nb(NIc, 4), bt>>>(nodeW + Dc * Dc, 1);
    nodeCombine_k<<<nb(NUc, 4), bt>>>(nodeW + Dc * Dc, 0);

    writeOut_k<<<nb(NUD + NID, TB), TB>>>(out);
}